// round 12
// baseline (speedup 1.0000x reference)
#include <cuda_runtime.h>
#include <cuda_fp16.h>
#include <cstdint>
#include <cstring>

#define NN     20000
#define EE     640000
#define ETOT   660000      // EE + NN self loops
#define GG     64
#define FIN    128
#define FOUT   128
#define HEADS  4
#define HID    64
#define HC12   256         // HEADS*HID

// ---------------------------------------------------------------------------
// Scratch (device globals; zero-initialized at module load)
// ---------------------------------------------------------------------------
__device__ __half g_h16[(size_t)NN * HC12];   // GEMM out (gather input)
__device__ __half g_b16[(size_t)NN * HC12];   // gather out (next GEMM input)
__device__ __half g_x16[(size_t)NN * FIN];    // x in fp16
__device__ __half g_w16[131072];              // W1|W2|W3 in fp16
__device__ float  g_asA[(size_t)NN * HEADS];
__device__ float  g_adA[(size_t)NN * HEADS];
__device__ float  g_asB[(size_t)NN * HEADS];
__device__ float  g_adB[(size_t)NN * HEADS];
__device__ int    g_deg[NN];                  // invariant: zero at call entry
__device__ int    g_off[NN + 1];
__device__ int    g_rank[ETOT];
__device__ int    g_csr_src[ETOT];

// ---------------------------------------------------------------------------
// Helpers
// ---------------------------------------------------------------------------
__device__ __forceinline__ uint32_t h2_as_u32(__half2 h) {
    uint32_t u;
    memcpy(&u, &h, 4);
    return u;
}

__device__ __forceinline__ void mma_f16(float* c, const uint32_t* a, const uint32_t* b) {
    asm volatile(
        "mma.sync.aligned.m16n8k16.row.col.f32.f16.f16.f32 "
        "{%0,%1,%2,%3}, {%4,%5,%6,%7}, {%8,%9}, {%0,%1,%2,%3};"
        : "+f"(c[0]), "+f"(c[1]), "+f"(c[2]), "+f"(c[3])
        : "r"(a[0]), "r"(a[1]), "r"(a[2]), "r"(a[3]), "r"(b[0]), "r"(b[1]));
}

__device__ __forceinline__ void ldsm_x4(uint32_t* r, uint32_t addr) {
    asm volatile("ldmatrix.sync.aligned.m8n8.x4.shared.b16 {%0,%1,%2,%3}, [%4];"
                 : "=r"(r[0]), "=r"(r[1]), "=r"(r[2]), "=r"(r[3]) : "r"(addr));
}

__device__ __forceinline__ void ldsm_x4_trans(uint32_t* r, uint32_t addr) {
    asm volatile("ldmatrix.sync.aligned.m8n8.x4.trans.shared.b16 {%0,%1,%2,%3}, [%4];"
                 : "=r"(r[0]), "=r"(r[1]), "=r"(r[2]), "=r"(r[3]) : "r"(addr));
}

__device__ __forceinline__ void h8_accum(float* acc, uint4 v, float ex) {
    float2 f0 = __half22float2(*reinterpret_cast<__half2*>(&v.x));
    float2 f1 = __half22float2(*reinterpret_cast<__half2*>(&v.y));
    float2 f2 = __half22float2(*reinterpret_cast<__half2*>(&v.z));
    float2 f3 = __half22float2(*reinterpret_cast<__half2*>(&v.w));
    acc[0] += ex * f0.x; acc[1] += ex * f0.y;
    acc[2] += ex * f1.x; acc[3] += ex * f1.y;
    acc[4] += ex * f2.x; acc[5] += ex * f2.y;
    acc[6] += ex * f3.x; acc[7] += ex * f3.y;
}

__device__ __forceinline__ void h4_accum(float* acc, uint2 v, float ex) {
    float2 f0 = __half22float2(*reinterpret_cast<__half2*>(&v.x));
    float2 f1 = __half22float2(*reinterpret_cast<__half2*>(&v.y));
    acc[0] += ex * f0.x; acc[1] += ex * f0.y;
    acc[2] += ex * f1.x; acc[3] += ex * f1.y;
}

// ---------------------------------------------------------------------------
// cvt kernels: main = x + W1 (critical path); side = W2 + W3
// ---------------------------------------------------------------------------
__global__ void cvt_main_kernel(const float4* __restrict__ x, uint2* __restrict__ x16,
                                const float4* __restrict__ W1, uint2* __restrict__ w16,
                                float* __restrict__ asA, float* __restrict__ adA)
{
    int t = blockIdx.x * blockDim.x + threadIdx.x;
    if (t < NN * HEADS) { asA[t] = 0.f; adA[t] = 0.f; }
    if (t < NN * FIN / 4) {
        float4 v = x[t];
        uint2 o;
        o.x = h2_as_u32(__floats2half2_rn(v.x, v.y));
        o.y = h2_as_u32(__floats2half2_rn(v.z, v.w));
        x16[t] = o;
    }
    if (t < 8192) {
        float4 v = W1[t];
        uint2 o;
        o.x = h2_as_u32(__floats2half2_rn(v.x, v.y));
        o.y = h2_as_u32(__floats2half2_rn(v.z, v.w));
        w16[t] = o;
    }
}

__global__ void cvt_side_kernel(const float4* __restrict__ W2, const float4* __restrict__ W3,
                                uint2* __restrict__ w16,
                                float* __restrict__ asB, float* __restrict__ adB)
{
    int t = blockIdx.x * blockDim.x + threadIdx.x;
    if (t < NN * HEADS) { asB[t] = 0.f; adB[t] = 0.f; }
    if (t < 24576) {
        float4 v = (t < 16384) ? W2[t] : W3[t - 16384];
        uint2 o;
        o.x = h2_as_u32(__floats2half2_rn(v.x, v.y));
        o.y = h2_as_u32(__floats2half2_rn(v.z, v.w));
        w16[8192 + t] = o;
    }
}

// ---------------------------------------------------------------------------
// fp16 tensor-core GEMM, 3-stage cp.async pipeline, ldmatrix fragments.
// C16[N,M] = A[N,K]*B[K,M]; fused alpha epilogue into outs/outd (atomic).
// BM=128, BN=64, BK=32; 8 warps x (32x32); mma m16n8k16.
// ---------------------------------------------------------------------------
__global__ __launch_bounds__(256) void gemm_tc_kernel(
    const __half* __restrict__ A, const __half* __restrict__ B,
    __half* __restrict__ C, int N, int K, int M,
    const float* __restrict__ avs, const float* __restrict__ avd,
    float* __restrict__ outs, float* __restrict__ outd, int H, int Cdim)
{
    __shared__ __half As[3][128][40];   // stride 40 halves -> conflict-free ldmatrix
    __shared__ __half Bs[3][32][72];    // stride 72 halves -> conflict-free ldmatrix.trans

    const int tid  = threadIdx.x;
    const int lane = tid & 31;
    const int warp = tid >> 5;
    const int wr   = (warp & 3) * 32;
    const int wc   = (warp >> 2) * 32;
    const int rowBase = blockIdx.y * 128;
    const int colBase = blockIdx.x * 64;
    const int g  = lane >> 2;
    const int tg = lane & 3;
    const int grp  = lane >> 3;
    const int lrow = lane & 7;

    const int ar0 = tid >> 2;            // A: 4 chunks of 8 halves per row
    const int ac8 = (tid & 3) * 8;
    const int brr = tid >> 3;            // B: 8 chunks per row (64 halves)
    const int bc8 = (tid & 7) * 8;

    float acc[2][4][4];
#pragma unroll
    for (int i = 0; i < 2; i++)
#pragma unroll
        for (int j = 0; j < 4; j++)
#pragma unroll
            for (int k = 0; k < 4; k++) acc[i][j][k] = 0.f;

    auto stage = [&](int k0, int st) {
#pragma unroll
        for (int l = 0; l < 2; l++) {
            int r  = ar0 + l * 64;
            int gr = rowBase + r;
            uint32_t dst = (uint32_t)__cvta_generic_to_shared(&As[st][r][ac8]);
            const __half* src = (gr < N) ? &A[(size_t)gr * K + k0 + ac8] : A;
            int sz = (gr < N) ? 16 : 0;
            asm volatile("cp.async.cg.shared.global [%0], [%1], 16, %2;"
                         :: "r"(dst), "l"(src), "r"(sz));
        }
        {
            uint32_t dst = (uint32_t)__cvta_generic_to_shared(&Bs[st][brr][bc8]);
            const __half* src = &B[(size_t)(k0 + brr) * M + colBase + bc8];
            asm volatile("cp.async.cg.shared.global [%0], [%1], 16;"
                         :: "r"(dst), "l"(src));
        }
        asm volatile("cp.async.commit_group;");
    };

    const uint32_t asb = (uint32_t)__cvta_generic_to_shared(&As[0][0][0]);
    const uint32_t bsb = (uint32_t)__cvta_generic_to_shared(&Bs[0][0][0]);
    const uint32_t asStage = 128 * 40 * 2;
    const uint32_t bsStage = 32 * 72 * 2;

    const int T = K >> 5;      // 4 or 8 tiles
    stage(0, 0);
    if (T > 1) stage(32, 1);
    for (int it = 0; it < T; it++) {
        if (it + 2 < T) {
            int nst = (it + 2) % 3;
            stage((it + 2) << 5, nst);
            asm volatile("cp.async.wait_group 2;");
        } else if (it + 1 < T) {
            asm volatile("cp.async.wait_group 1;");
        } else {
            asm volatile("cp.async.wait_group 0;");
        }
        __syncthreads();
        int st = it % 3;
        uint32_t aS = asb + st * asStage;
        uint32_t bS = bsb + st * bsStage;
#pragma unroll
        for (int kk = 0; kk < 32; kk += 16) {
            uint32_t a[2][4], b[2][4];
#pragma unroll
            for (int i = 0; i < 2; i++) {
                int row = wr + i * 16 + lrow + ((grp & 1) << 3);
                int col = kk + ((grp & 2) << 2);
                ldsm_x4(a[i], aS + (row * 40 + col) * 2);
            }
#pragma unroll
            for (int jp = 0; jp < 2; jp++) {
                int krow = kk + ((grp & 1) << 3) + lrow;
                int ncol = wc + jp * 16 + ((grp & 2) << 2);
                ldsm_x4_trans(b[jp], bS + (krow * 72 + ncol) * 2);
            }
#pragma unroll
            for (int i = 0; i < 2; i++)
#pragma unroll
                for (int j = 0; j < 4; j++)
                    mma_f16(acc[i][j], a[i], &b[j >> 1][(j & 1) * 2]);
        }
        __syncthreads();
    }

    // ---- writeback fp16 C ----
#pragma unroll
    for (int i = 0; i < 2; i++) {
        int r0 = rowBase + wr + i * 16 + g;
#pragma unroll
        for (int j = 0; j < 4; j++) {
            int c0 = colBase + wc + j * 8 + tg * 2;
            if (r0 < N) {
                __half2 v = __floats2half2_rn(acc[i][j][0], acc[i][j][1]);
                *reinterpret_cast<__half2*>(&C[(size_t)r0 * M + c0]) = v;
            }
            if (r0 + 8 < N) {
                __half2 v = __floats2half2_rn(acc[i][j][2], acc[i][j][3]);
                *reinterpret_cast<__half2*>(&C[(size_t)(r0 + 8) * M + c0]) = v;
            }
        }
    }

    // ---- fused alpha partials ----
    const int head = colBase / Cdim;
    float ps[2][2], pd[2][2];
#pragma unroll
    for (int i = 0; i < 2; i++) { ps[i][0]=ps[i][1]=pd[i][0]=pd[i][1]=0.f; }
#pragma unroll
    for (int j = 0; j < 4; j++) {
        int c0 = colBase + wc + j * 8 + tg * 2;
        float s0 = avs[c0], s1 = avs[c0 + 1];
        float d0 = avd[c0], d1 = avd[c0 + 1];
#pragma unroll
        for (int i = 0; i < 2; i++) {
            ps[i][0] += acc[i][j][0] * s0 + acc[i][j][1] * s1;
            pd[i][0] += acc[i][j][0] * d0 + acc[i][j][1] * d1;
            ps[i][1] += acc[i][j][2] * s0 + acc[i][j][3] * s1;
            pd[i][1] += acc[i][j][2] * d0 + acc[i][j][3] * d1;
        }
    }
#pragma unroll
    for (int o = 1; o < 4; o <<= 1) {
#pragma unroll
        for (int i = 0; i < 2; i++) {
#pragma unroll
            for (int sr = 0; sr < 2; sr++) {
                ps[i][sr] += __shfl_xor_sync(0xffffffffu, ps[i][sr], o);
                pd[i][sr] += __shfl_xor_sync(0xffffffffu, pd[i][sr], o);
            }
        }
    }
    if (tg == 0) {
#pragma unroll
        for (int i = 0; i < 2; i++) {
            int ra = rowBase + wr + i * 16 + g;
            if (ra < N) {
                atomicAdd(&outs[ra * H + head], ps[i][0]);
                atomicAdd(&outd[ra * H + head], pd[i][0]);
            }
            int rb = ra + 8;
            if (rb < N) {
                atomicAdd(&outs[rb * H + head], ps[i][1]);
                atomicAdd(&outd[rb * H + head], pd[i][1]);
            }
        }
    }
}

// ---------------------------------------------------------------------------
// CSR build
// ---------------------------------------------------------------------------
__global__ void csr_count_kernel(const int* __restrict__ ei, int* __restrict__ deg,
                                 int* __restrict__ rank)
{
    int t = blockIdx.x * blockDim.x + threadIdx.x;
    if (t >= ETOT) return;
    int d = (t < EE) ? ei[EE + t] : (t - EE);
    rank[t] = atomicAdd(&deg[d], 1);
}

__global__ __launch_bounds__(1024) void csr_scan_kernel(
    int* __restrict__ deg, int* __restrict__ off)
{
    const int PER = 20;
    __shared__ int warpSums[32];
    int t    = threadIdx.x;
    int lane = t & 31, wid = t >> 5;
    int base = t * PER;

    int v[PER];
    int s = 0;
#pragma unroll
    for (int i = 0; i < PER; i++) {
        int idx = base + i;
        int x = (idx < NN) ? deg[idx] : 0;
        if (idx < NN) deg[idx] = 0;
        v[i] = s;
        s += x;
    }
    int incl = s;
#pragma unroll
    for (int o = 1; o < 32; o <<= 1) {
        int u = __shfl_up_sync(0xffffffffu, incl, o);
        if (lane >= o) incl += u;
    }
    if (lane == 31) warpSums[wid] = incl;
    __syncthreads();
    if (wid == 0) {
        int ws = warpSums[lane];
#pragma unroll
        for (int o = 1; o < 32; o <<= 1) {
            int u = __shfl_up_sync(0xffffffffu, ws, o);
            if (lane >= o) ws += u;
        }
        warpSums[lane] = ws;
    }
    __syncthreads();
    int warpPrefix  = (wid == 0) ? 0 : warpSums[wid - 1];
    int threadExcl  = warpPrefix + incl - s;
#pragma unroll
    for (int i = 0; i < PER; i++) {
        int idx = base + i;
        if (idx < NN) off[idx] = threadExcl + v[i];
    }
    if (t == 0) off[NN] = ETOT;
}

__global__ void csr_scatter_kernel(const int* __restrict__ ei,
                                   const int* __restrict__ off,
                                   const int* __restrict__ rank,
                                   int* __restrict__ csr_src)
{
    int t = blockIdx.x * blockDim.x + threadIdx.x;
    if (t >= ETOT) return;
    int s, d;
    if (t < EE) { s = ei[t]; d = ei[EE + t]; }
    else        { s = t - EE; d = s; }
    csr_src[off[d] + rank[t]] = s;
}

// ---------------------------------------------------------------------------
// GAT aggregation (H=4, C=64): ONE warp per dst; unroll-4; fp16 in AND out.
// ---------------------------------------------------------------------------
__global__ __launch_bounds__(256) void gat_gather4_kernel(
    const int* __restrict__ off, const int* __restrict__ csr_src,
    const __half* __restrict__ h,
    const float* __restrict__ as_, const float* __restrict__ ad_,
    const float* __restrict__ bias, __half* __restrict__ out)
{
    int gt   = blockIdx.x * blockDim.x + threadIdx.x;
    int d    = gt >> 5;
    int lane = gt & 31;
    if (d >= NN) return;

    const int head = lane >> 3;
    const uint4* hb = reinterpret_cast<const uint4*>(h);
    float adv = ad_[d * 4 + head];

    float acc[8];
#pragma unroll
    for (int k = 0; k < 8; k++) acc[k] = 0.f;
    float den = 0.f;

    int a   = off[d];
    int end = off[d + 1];
    for (; a + 3 < end; a += 4) {
        int s0 = csr_src[a];
        int s1 = csr_src[a + 1];
        int s2 = csr_src[a + 2];
        int s3 = csr_src[a + 3];
        float e0 = as_[s0 * 4 + head] + adv;
        float e1 = as_[s1 * 4 + head] + adv;
        float e2 = as_[s2 * 4 + head] + adv;
        float e3 = as_[s3 * 4 + head] + adv;
        uint4 v0 = hb[(size_t)s0 * 32 + lane];
        uint4 v1 = hb[(size_t)s1 * 32 + lane];
        uint4 v2 = hb[(size_t)s2 * 32 + lane];
        uint4 v3 = hb[(size_t)s3 * 32 + lane];
        e0 = e0 > 0.f ? e0 : 0.2f * e0;
        e1 = e1 > 0.f ? e1 : 0.2f * e1;
        e2 = e2 > 0.f ? e2 : 0.2f * e2;
        e3 = e3 > 0.f ? e3 : 0.2f * e3;
        float x0 = __expf(e0);
        float x1 = __expf(e1);
        float x2 = __expf(e2);
        float x3 = __expf(e3);
        h8_accum(acc, v0, x0);
        h8_accum(acc, v1, x1);
        h8_accum(acc, v2, x2);
        h8_accum(acc, v3, x3);
        den += (x0 + x1) + (x2 + x3);
    }
    for (; a < end; a++) {
        int s = csr_src[a];
        float e = as_[s * 4 + head] + adv;
        uint4 v = hb[(size_t)s * 32 + lane];
        e = e > 0.f ? e : 0.2f * e;
        float ex = __expf(e);
        h8_accum(acc, v, ex);
        den += ex;
    }

    float r = 1.f / (den + 1e-16f);
    float4 b0 = *reinterpret_cast<const float4*>(&bias[lane * 8]);
    float4 b1 = *reinterpret_cast<const float4*>(&bias[lane * 8 + 4]);
    float o[8];
    o[0] = acc[0] * r + b0.x; o[1] = acc[1] * r + b0.y;
    o[2] = acc[2] * r + b0.z; o[3] = acc[3] * r + b0.w;
    o[4] = acc[4] * r + b1.x; o[5] = acc[5] * r + b1.y;
    o[6] = acc[6] * r + b1.z; o[7] = acc[7] * r + b1.w;
#pragma unroll
    for (int k = 0; k < 8; k++) o[k] = o[k] > 0.f ? o[k] : expm1f(o[k]);

    uint4 ov;
    ov.x = h2_as_u32(__floats2half2_rn(o[0], o[1]));
    ov.y = h2_as_u32(__floats2half2_rn(o[2], o[3]));
    ov.z = h2_as_u32(__floats2half2_rn(o[4], o[5]));
    ov.w = h2_as_u32(__floats2half2_rn(o[6], o[7]));
    reinterpret_cast<uint4*>(out + (size_t)d * HC12)[lane] = ov;
}

// ---------------------------------------------------------------------------
// GAT aggregation (H=1, C=128): ONE warp per dst; unroll-4; fp32 out.
// ---------------------------------------------------------------------------
__global__ __launch_bounds__(256) void gat_gather1_kernel(
    const int* __restrict__ off, const int* __restrict__ csr_src,
    const __half* __restrict__ h,
    const float* __restrict__ as_, const float* __restrict__ ad_,
    const float* __restrict__ bias, float* __restrict__ out)
{
    int gt   = blockIdx.x * blockDim.x + threadIdx.x;
    int d    = gt >> 5;
    int lane = gt & 31;
    if (d >= NN) return;

    const uint2* hb = reinterpret_cast<const uint2*>(h);
    float adv = ad_[d];
    float acc[4] = {0.f, 0.f, 0.f, 0.f};
    float den = 0.f;

    int a   = off[d];
    int end = off[d + 1];
    for (; a + 3 < end; a += 4) {
        int s0 = csr_src[a];
        int s1 = csr_src[a + 1];
        int s2 = csr_src[a + 2];
        int s3 = csr_src[a + 3];
        float e0 = as_[s0] + adv;
        float e1 = as_[s1] + adv;
        float e2 = as_[s2] + adv;
        float e3 = as_[s3] + adv;
        uint2 v0 = hb[(size_t)s0 * 32 + lane];
        uint2 v1 = hb[(size_t)s1 * 32 + lane];
        uint2 v2 = hb[(size_t)s2 * 32 + lane];
        uint2 v3 = hb[(size_t)s3 * 32 + lane];
        e0 = e0 > 0.f ? e0 : 0.2f * e0;
        e1 = e1 > 0.f ? e1 : 0.2f * e1;
        e2 = e2 > 0.f ? e2 : 0.2f * e2;
        e3 = e3 > 0.f ? e3 : 0.2f * e3;
        float x0 = __expf(e0);
        float x1 = __expf(e1);
        float x2 = __expf(e2);
        float x3 = __expf(e3);
        h4_accum(acc, v0, x0);
        h4_accum(acc, v1, x1);
        h4_accum(acc, v2, x2);
        h4_accum(acc, v3, x3);
        den += (x0 + x1) + (x2 + x3);
    }
    for (; a < end; a++) {
        int s = csr_src[a];
        float e = as_[s] + adv;
        uint2 v = hb[(size_t)s * 32 + lane];
        e = e > 0.f ? e : 0.2f * e;
        float ex = __expf(e);
        h4_accum(acc, v, ex);
        den += ex;
    }

    float r = 1.f / (den + 1e-16f);
    float4 b = *reinterpret_cast<const float4*>(&bias[lane * 4]);
    float4 o;
    o.x = acc[0] * r + b.x; o.y = acc[1] * r + b.y;
    o.z = acc[2] * r + b.z; o.w = acc[3] * r + b.w;
    reinterpret_cast<float4*>(out + (size_t)d * FOUT)[lane] = o;
}

// ---------------------------------------------------------------------------
// Segmented global mean pool (batch sorted)
// ---------------------------------------------------------------------------
__global__ __launch_bounds__(128) void pool_kernel(
    const float* __restrict__ h, const int* __restrict__ bat,
    float* __restrict__ out_emb)
{
    int g = blockIdx.x;
    int c = threadIdx.x;

    int lo = 0, hi = NN;
    while (lo < hi) { int m = (lo + hi) >> 1; if (bat[m] < g) lo = m + 1; else hi = m; }
    int start = lo;
    lo = 0; hi = NN;
    while (lo < hi) { int m = (lo + hi) >> 1; if (bat[m] < g + 1) lo = m + 1; else hi = m; }
    int end = lo;

    float s0 = 0.f, s1 = 0.f, s2 = 0.f, s3 = 0.f;
    int n = start;
    for (; n + 3 < end; n += 4) {
        s0 += h[(size_t)n * FOUT + c];
        s1 += h[(size_t)(n + 1) * FOUT + c];
        s2 += h[(size_t)(n + 2) * FOUT + c];
        s3 += h[(size_t)(n + 3) * FOUT + c];
    }
    for (; n < end; n++) s0 += h[(size_t)n * FOUT + c];
    float s = (s0 + s1) + (s2 + s3);
    out_emb[g * FOUT + c] = s / fmaxf((float)(end - start), 1.f);
}

// ---------------------------------------------------------------------------
// zero alpha buffers (tiny; used between layers on the side stream)
// ---------------------------------------------------------------------------
__global__ void zero_alpha_kernel(float* __restrict__ a, float* __restrict__ b)
{
    int t = blockIdx.x * blockDim.x + threadIdx.x;
    if (t < NN * HEADS) { a[t] = 0.f; b[t] = 0.f; }
}

// ---------------------------------------------------------------------------
// Launch
// ---------------------------------------------------------------------------
extern "C" void kernel_launch(void* const* d_in, const int* in_sizes, int n_in,
                              void* d_out, int out_size)
{
    const float* x   = (const float*)d_in[0];
    const int*   ei  = (const int*)d_in[1];
    const int*   bat = (const int*)d_in[2];
    const float* W1  = (const float*)d_in[3];
    const float* as1 = (const float*)d_in[4];
    const float* ad1 = (const float*)d_in[5];
    const float* b1  = (const float*)d_in[6];
    const float* W2  = (const float*)d_in[7];
    const float* as2 = (const float*)d_in[8];
    const float* ad2 = (const float*)d_in[9];
    const float* b2  = (const float*)d_in[10];
    const float* W3  = (const float*)d_in[11];
    const float* as3 = (const float*)d_in[12];
    const float* ad3 = (const float*)d_in[13];
    const float* b3  = (const float*)d_in[14];

    float* out     = (float*)d_out;
    float* out_emb = out;                 // [G, FOUT]
    float* out_h   = out + GG * FOUT;     // [N, FOUT]

    __half *h16, *b16, *x16, *w16;
    float *asA, *adA, *asB, *adB;
    int *deg, *off, *rank, *csr_src;
    cudaGetSymbolAddress((void**)&h16,  g_h16);
    cudaGetSymbolAddress((void**)&b16,  g_b16);
    cudaGetSymbolAddress((void**)&x16,  g_x16);
    cudaGetSymbolAddress((void**)&w16,  g_w16);
    cudaGetSymbolAddress((void**)&asA,  g_asA);
    cudaGetSymbolAddress((void**)&adA,  g_adA);
    cudaGetSymbolAddress((void**)&asB,  g_asB);
    cudaGetSymbolAddress((void**)&adB,  g_adB);
    cudaGetSymbolAddress((void**)&deg,  g_deg);
    cudaGetSymbolAddress((void**)&off,  g_off);
    cudaGetSymbolAddress((void**)&rank, g_rank);
    cudaGetSymbolAddress((void**)&csr_src, g_csr_src);

    __half* w16_1 = w16;
    __half* w16_2 = w16 + 32768;
    __half* w16_3 = w16 + 98304;

    static cudaStream_t sideStream = nullptr;
    static cudaEvent_t evFork = nullptr, evJoin = nullptr, evJoin2 = nullptr;
    if (sideStream == nullptr) {
        cudaStreamCreateWithFlags(&sideStream, cudaStreamNonBlocking);
        cudaEventCreateWithFlags(&evFork, cudaEventDisableTiming);
        cudaEventCreateWithFlags(&evJoin, cudaEventDisableTiming);
        cudaEventCreateWithFlags(&evJoin2, cudaEventDisableTiming);
    }

    // --- fork: CSR build + W2/W3 cvt + asB/adB zero on side stream ---
    cudaEventRecord(evFork, 0);
    cudaStreamWaitEvent(sideStream, evFork, 0);
    csr_count_kernel<<<(ETOT + 255) / 256, 256, 0, sideStream>>>(ei, deg, rank);
    csr_scan_kernel<<<1, 1024, 0, sideStream>>>(deg, off);
    csr_scatter_kernel<<<(ETOT + 255) / 256, 256, 0, sideStream>>>(ei, off, rank, csr_src);
    cvt_side_kernel<<<(NN * HEADS + 255) / 256, 256, 0, sideStream>>>(
        (const float4*)W2, (const float4*)W3, (uint2*)w16, asB, adB);
    cudaEventRecord(evJoin, sideStream);

    const int nby = (NN + 127) / 128;
    const int gatherGrid = (NN * 32 + 255) / 256;

    // --- main stream: cvt(x,W1) + layer-1 GEMM overlap with side work ---
    cvt_main_kernel<<<(NN * FIN / 4 + 255) / 256, 256>>>(
        (const float4*)x, (uint2*)x16, (const float4*)W1, (uint2*)w16, asA, adA);
    gemm_tc_kernel<<<dim3(HC12 / 64, nby), 256>>>(x16, w16_1, h16, NN, FIN, HC12,
                                                  as1, ad1, asA, adA, HEADS, HID);

    // --- join: gathers need CSR; GEMM2 needs w16_2/asB/adB ---
    cudaStreamWaitEvent(0, evJoin, 0);

    gat_gather4_kernel<<<gatherGrid, 256>>>(off, csr_src, h16, asA, adA, b1, b16);

    // side: re-zero asA/adA for layer 3 while GEMM2/gather2 run on main
    cudaEventRecord(evFork, 0);
    cudaStreamWaitEvent(sideStream, evFork, 0);
    zero_alpha_kernel<<<(NN * HEADS + 255) / 256, 256, 0, sideStream>>>(asA, adA);
    cudaEventRecord(evJoin2, sideStream);

    // --- Layer 2 ---
    gemm_tc_kernel<<<dim3(HC12 / 64, nby), 256>>>(b16, w16_2, h16, NN, HC12, HC12,
                                                  as2, ad2, asB, adB, HEADS, HID);
    gat_gather4_kernel<<<gatherGrid, 256>>>(off, csr_src, h16, asB, adB, b2, b16);

    cudaStreamWaitEvent(0, evJoin2, 0);

    // --- Layer 3 ---
    gemm_tc_kernel<<<dim3(FOUT / 64, nby), 256>>>(b16, w16_3, h16, NN, HC12, FOUT,
                                                  as3, ad3, asA, adA, 1, FOUT);
    gat_gather1_kernel<<<gatherGrid, 256>>>(off, csr_src, h16, asA, adA, b3, out_h);

    // --- segmented global mean pool ---
    pool_kernel<<<GG, 128>>>(out_h, bat, out_emb);
}

// round 16
// speedup vs baseline: 1.0041x; 1.0041x over previous
#include <cuda_runtime.h>
#include <cuda_fp16.h>
#include <cstdint>
#include <cstring>

#define NN     20000
#define EE     640000
#define ETOT   660000      // EE + NN self loops
#define GG     64
#define FIN    128
#define FOUT   128
#define HEADS  4
#define HID    64
#define HC12   256         // HEADS*HID

// ---------------------------------------------------------------------------
// Scratch (device globals; zero-initialized at module load)
// ---------------------------------------------------------------------------
__device__ __half g_h16[(size_t)NN * HC12];   // GEMM out (gather input)
__device__ __half g_b16[(size_t)NN * HC12];   // gather out (next GEMM input)
__device__ __half g_w16[131072];              // W1|W2|W3 in fp16
__device__ float  g_asA[(size_t)NN * HEADS];
__device__ float  g_adA[(size_t)NN * HEADS];
__device__ float  g_asB[(size_t)NN * HEADS];
__device__ float  g_adB[(size_t)NN * HEADS];
__device__ int    g_deg[NN];                  // invariant: zero at call entry
__device__ int    g_off[NN + 1];
__device__ int    g_rank[ETOT];
__device__ int    g_csr_src[ETOT];

// ---------------------------------------------------------------------------
// Helpers
// ---------------------------------------------------------------------------
__device__ __forceinline__ uint32_t h2_as_u32(__half2 h) {
    uint32_t u;
    memcpy(&u, &h, 4);
    return u;
}

__device__ __forceinline__ void mma_f16(float* c, const uint32_t* a, const uint32_t* b) {
    asm volatile(
        "mma.sync.aligned.m16n8k16.row.col.f32.f16.f16.f32 "
        "{%0,%1,%2,%3}, {%4,%5,%6,%7}, {%8,%9}, {%0,%1,%2,%3};"
        : "+f"(c[0]), "+f"(c[1]), "+f"(c[2]), "+f"(c[3])
        : "r"(a[0]), "r"(a[1]), "r"(a[2]), "r"(a[3]), "r"(b[0]), "r"(b[1]));
}

__device__ __forceinline__ void ldsm_x4(uint32_t* r, uint32_t addr) {
    asm volatile("ldmatrix.sync.aligned.m8n8.x4.shared.b16 {%0,%1,%2,%3}, [%4];"
                 : "=r"(r[0]), "=r"(r[1]), "=r"(r[2]), "=r"(r[3]) : "r"(addr));
}

__device__ __forceinline__ void ldsm_x4_trans(uint32_t* r, uint32_t addr) {
    asm volatile("ldmatrix.sync.aligned.m8n8.x4.trans.shared.b16 {%0,%1,%2,%3}, [%4];"
                 : "=r"(r[0]), "=r"(r[1]), "=r"(r[2]), "=r"(r[3]) : "r"(addr));
}

__device__ __forceinline__ void h8_accum(float* acc, uint4 v, float ex) {
    float2 f0 = __half22float2(*reinterpret_cast<__half2*>(&v.x));
    float2 f1 = __half22float2(*reinterpret_cast<__half2*>(&v.y));
    float2 f2 = __half22float2(*reinterpret_cast<__half2*>(&v.z));
    float2 f3 = __half22float2(*reinterpret_cast<__half2*>(&v.w));
    acc[0] += ex * f0.x; acc[1] += ex * f0.y;
    acc[2] += ex * f1.x; acc[3] += ex * f1.y;
    acc[4] += ex * f2.x; acc[5] += ex * f2.y;
    acc[6] += ex * f3.x; acc[7] += ex * f3.y;
}

__device__ __forceinline__ void h4_accum(float* acc, uint2 v, float ex) {
    float2 f0 = __half22float2(*reinterpret_cast<__half2*>(&v.x));
    float2 f1 = __half22float2(*reinterpret_cast<__half2*>(&v.y));
    acc[0] += ex * f0.x; acc[1] += ex * f0.y;
    acc[2] += ex * f1.x; acc[3] += ex * f1.y;
}

// ---------------------------------------------------------------------------
// Side-stream cvt kernels
// ---------------------------------------------------------------------------
__global__ void cvt_w1_kernel(const float4* __restrict__ W1, uint2* __restrict__ w16,
                              float* __restrict__ asA, float* __restrict__ adA)
{
    int t = blockIdx.x * blockDim.x + threadIdx.x;
    if (t < NN * HEADS) { asA[t] = 0.f; adA[t] = 0.f; }
    if (t < 8192) {
        float4 v = W1[t];
        uint2 o;
        o.x = h2_as_u32(__floats2half2_rn(v.x, v.y));
        o.y = h2_as_u32(__floats2half2_rn(v.z, v.w));
        w16[t] = o;
    }
}

__global__ void cvt_side_kernel(const float4* __restrict__ W2, const float4* __restrict__ W3,
                                uint2* __restrict__ w16,
                                float* __restrict__ asB, float* __restrict__ adB)
{
    int t = blockIdx.x * blockDim.x + threadIdx.x;
    if (t < NN * HEADS) { asB[t] = 0.f; adB[t] = 0.f; }
    if (t < 24576) {
        float4 v = (t < 16384) ? W2[t] : W3[t - 16384];
        uint2 o;
        o.x = h2_as_u32(__floats2half2_rn(v.x, v.y));
        o.y = h2_as_u32(__floats2half2_rn(v.z, v.w));
        w16[8192 + t] = o;
    }
}

// ---------------------------------------------------------------------------
// Shared epilogue: fp16 C writeback + fused alpha partials
// ---------------------------------------------------------------------------
__device__ __forceinline__ void gemm_epilogue(
    float acc[2][4][4], __half* C, int N, int M,
    const float* avs, const float* avd, float* outs, float* outd,
    int H, int Cdim, int rowBase, int colBase, int wr, int wc, int g, int tg)
{
#pragma unroll
    for (int i = 0; i < 2; i++) {
        int r0 = rowBase + wr + i * 16 + g;
#pragma unroll
        for (int j = 0; j < 4; j++) {
            int c0 = colBase + wc + j * 8 + tg * 2;
            if (r0 < N) {
                __half2 v = __floats2half2_rn(acc[i][j][0], acc[i][j][1]);
                *reinterpret_cast<__half2*>(&C[(size_t)r0 * M + c0]) = v;
            }
            if (r0 + 8 < N) {
                __half2 v = __floats2half2_rn(acc[i][j][2], acc[i][j][3]);
                *reinterpret_cast<__half2*>(&C[(size_t)(r0 + 8) * M + c0]) = v;
            }
        }
    }

    const int head = colBase / Cdim;
    float ps[2][2], pd[2][2];
#pragma unroll
    for (int i = 0; i < 2; i++) { ps[i][0]=ps[i][1]=pd[i][0]=pd[i][1]=0.f; }
#pragma unroll
    for (int j = 0; j < 4; j++) {
        int c0 = colBase + wc + j * 8 + tg * 2;
        float s0 = avs[c0], s1 = avs[c0 + 1];
        float d0 = avd[c0], d1 = avd[c0 + 1];
#pragma unroll
        for (int i = 0; i < 2; i++) {
            ps[i][0] += acc[i][j][0] * s0 + acc[i][j][1] * s1;
            pd[i][0] += acc[i][j][0] * d0 + acc[i][j][1] * d1;
            ps[i][1] += acc[i][j][2] * s0 + acc[i][j][3] * s1;
            pd[i][1] += acc[i][j][2] * d0 + acc[i][j][3] * d1;
        }
    }
#pragma unroll
    for (int o = 1; o < 4; o <<= 1) {
#pragma unroll
        for (int i = 0; i < 2; i++) {
#pragma unroll
            for (int sr = 0; sr < 2; sr++) {
                ps[i][sr] += __shfl_xor_sync(0xffffffffu, ps[i][sr], o);
                pd[i][sr] += __shfl_xor_sync(0xffffffffu, pd[i][sr], o);
            }
        }
    }
    if (tg == 0) {
#pragma unroll
        for (int i = 0; i < 2; i++) {
            int ra = rowBase + wr + i * 16 + g;
            if (ra < N) {
                atomicAdd(&outs[ra * H + head], ps[i][0]);
                atomicAdd(&outd[ra * H + head], pd[i][0]);
            }
            int rb = ra + 8;
            if (rb < N) {
                atomicAdd(&outs[rb * H + head], ps[i][1]);
                atomicAdd(&outd[rb * H + head], pd[i][1]);
            }
        }
    }
}

// ---------------------------------------------------------------------------
// Layer-1 GEMM: A is fp32 (x), converted in-kernel. K=128, M=256 fixed.
// B pipeline: 3 stages (%3) — prefetch distance 2 must NOT alias live stage.
// ---------------------------------------------------------------------------
__global__ __launch_bounds__(256) void gemm1_tc_kernel(
    const float* __restrict__ A, const __half* __restrict__ B,
    __half* __restrict__ C,
    const float* __restrict__ avs, const float* __restrict__ avd,
    float* __restrict__ outs, float* __restrict__ outd)
{
    const int N = NN, K = FIN, M = HC12;
    __shared__ __half As[128][40];
    __shared__ __half Bs[3][32][72];

    const int tid  = threadIdx.x;
    const int lane = tid & 31;
    const int warp = tid >> 5;
    const int wr   = (warp & 3) * 32;
    const int wc   = (warp >> 2) * 32;
    const int rowBase = blockIdx.y * 128;
    const int colBase = blockIdx.x * 64;
    const int g  = lane >> 2;
    const int tg = lane & 3;
    const int grp  = lane >> 3;
    const int lrow = lane & 7;

    const int brr = tid >> 3;
    const int bc8 = (tid & 7) * 8;

    float acc[2][4][4];
#pragma unroll
    for (int i = 0; i < 2; i++)
#pragma unroll
        for (int j = 0; j < 4; j++)
#pragma unroll
            for (int k = 0; k < 4; k++) acc[i][j][k] = 0.f;

    auto stageB = [&](int k0, int st) {
        uint32_t dst = (uint32_t)__cvta_generic_to_shared(&Bs[st][brr][bc8]);
        const __half* src = &B[(size_t)(k0 + brr) * M + colBase + bc8];
        asm volatile("cp.async.cg.shared.global [%0], [%1], 16;"
                     :: "r"(dst), "l"(src));
        asm volatile("cp.async.commit_group;");
    };

    const uint32_t asb = (uint32_t)__cvta_generic_to_shared(&As[0][0]);
    const uint32_t bsb = (uint32_t)__cvta_generic_to_shared(&Bs[0][0][0]);
    const uint32_t bsStage = 32 * 72 * 2;

    const int T = K >> 5;   // 4
    stageB(0, 0);
    if (T > 1) stageB(32, 1);

    for (int it = 0; it < T; it++) {
        float4 av[4];
#pragma unroll
        for (int l = 0; l < 4; l++) {
            int idx = tid + l * 256;
            int r   = idx >> 3;
            int c4  = (idx & 7) * 4;
            int gr  = rowBase + r;
            av[l] = (gr < N)
                ? *reinterpret_cast<const float4*>(&A[(size_t)gr * K + (it << 5) + c4])
                : make_float4(0.f, 0.f, 0.f, 0.f);
        }
        __syncthreads();   // prior mma done reading As
#pragma unroll
        for (int l = 0; l < 4; l++) {
            int idx = tid + l * 256;
            int r   = idx >> 3;
            int c4  = (idx & 7) * 4;
            uint2 o;
            o.x = h2_as_u32(__floats2half2_rn(av[l].x, av[l].y));
            o.y = h2_as_u32(__floats2half2_rn(av[l].z, av[l].w));
            *reinterpret_cast<uint2*>(&As[r][c4]) = o;
        }
        if (it + 2 < T) {
            stageB((it + 2) << 5, (it + 2) % 3);   // distinct stage (3-deep ring)
            asm volatile("cp.async.wait_group 2;");
        } else if (it + 1 < T) {
            asm volatile("cp.async.wait_group 1;");
        } else {
            asm volatile("cp.async.wait_group 0;");
        }
        __syncthreads();

        int st = it % 3;
        uint32_t bS = bsb + st * bsStage;
#pragma unroll
        for (int kk = 0; kk < 32; kk += 16) {
            uint32_t a[2][4], b[2][4];
#pragma unroll
            for (int i = 0; i < 2; i++) {
                int row = wr + i * 16 + lrow + ((grp & 1) << 3);
                int col = kk + ((grp & 2) << 2);
                ldsm_x4(a[i], asb + (row * 40 + col) * 2);
            }
#pragma unroll
            for (int jp = 0; jp < 2; jp++) {
                int krow = kk + ((grp & 1) << 3) + lrow;
                int ncol = wc + jp * 16 + ((grp & 2) << 2);
                ldsm_x4_trans(b[jp], bS + (krow * 72 + ncol) * 2);
            }
#pragma unroll
            for (int i = 0; i < 2; i++)
#pragma unroll
                for (int j = 0; j < 4; j++)
                    mma_f16(acc[i][j], a[i], &b[j >> 1][(j & 1) * 2]);
        }
    }
    gemm_epilogue(acc, C, N, M, avs, avd, outs, outd, HEADS, HID,
                  rowBase, colBase, wr, wc, g, tg);
}

// ---------------------------------------------------------------------------
// fp16 GEMM (layers 2-3): 3-stage cp.async pipeline, ldmatrix fragments.
// ---------------------------------------------------------------------------
__global__ __launch_bounds__(256) void gemm_tc_kernel(
    const __half* __restrict__ A, const __half* __restrict__ B,
    __half* __restrict__ C, int N, int K, int M,
    const float* __restrict__ avs, const float* __restrict__ avd,
    float* __restrict__ outs, float* __restrict__ outd, int H, int Cdim)
{
    __shared__ __half As[3][128][40];
    __shared__ __half Bs[3][32][72];

    const int tid  = threadIdx.x;
    const int lane = tid & 31;
    const int warp = tid >> 5;
    const int wr   = (warp & 3) * 32;
    const int wc   = (warp >> 2) * 32;
    const int rowBase = blockIdx.y * 128;
    const int colBase = blockIdx.x * 64;
    const int g  = lane >> 2;
    const int tg = lane & 3;
    const int grp  = lane >> 3;
    const int lrow = lane & 7;

    const int ar0 = tid >> 2;
    const int ac8 = (tid & 3) * 8;
    const int brr = tid >> 3;
    const int bc8 = (tid & 7) * 8;

    float acc[2][4][4];
#pragma unroll
    for (int i = 0; i < 2; i++)
#pragma unroll
        for (int j = 0; j < 4; j++)
#pragma unroll
            for (int k = 0; k < 4; k++) acc[i][j][k] = 0.f;

    auto stage = [&](int k0, int st) {
#pragma unroll
        for (int l = 0; l < 2; l++) {
            int r  = ar0 + l * 64;
            int gr = rowBase + r;
            uint32_t dst = (uint32_t)__cvta_generic_to_shared(&As[st][r][ac8]);
            const __half* src = (gr < N) ? &A[(size_t)gr * K + k0 + ac8] : A;
            int sz = (gr < N) ? 16 : 0;
            asm volatile("cp.async.cg.shared.global [%0], [%1], 16, %2;"
                         :: "r"(dst), "l"(src), "r"(sz));
        }
        {
            uint32_t dst = (uint32_t)__cvta_generic_to_shared(&Bs[st][brr][bc8]);
            const __half* src = &B[(size_t)(k0 + brr) * M + colBase + bc8];
            asm volatile("cp.async.cg.shared.global [%0], [%1], 16;"
                         :: "r"(dst), "l"(src));
        }
        asm volatile("cp.async.commit_group;");
    };

    const uint32_t asb = (uint32_t)__cvta_generic_to_shared(&As[0][0][0]);
    const uint32_t bsb = (uint32_t)__cvta_generic_to_shared(&Bs[0][0][0]);
    const uint32_t asStage = 128 * 40 * 2;
    const uint32_t bsStage = 32 * 72 * 2;

    const int T = K >> 5;
    stage(0, 0);
    if (T > 1) stage(32, 1);
    for (int it = 0; it < T; it++) {
        if (it + 2 < T) {
            int nst = (it + 2) % 3;
            stage((it + 2) << 5, nst);
            asm volatile("cp.async.wait_group 2;");
        } else if (it + 1 < T) {
            asm volatile("cp.async.wait_group 1;");
        } else {
            asm volatile("cp.async.wait_group 0;");
        }
        __syncthreads();
        int st = it % 3;
        uint32_t aS = asb + st * asStage;
        uint32_t bS = bsb + st * bsStage;
#pragma unroll
        for (int kk = 0; kk < 32; kk += 16) {
            uint32_t a[2][4], b[2][4];
#pragma unroll
            for (int i = 0; i < 2; i++) {
                int row = wr + i * 16 + lrow + ((grp & 1) << 3);
                int col = kk + ((grp & 2) << 2);
                ldsm_x4(a[i], aS + (row * 40 + col) * 2);
            }
#pragma unroll
            for (int jp = 0; jp < 2; jp++) {
                int krow = kk + ((grp & 1) << 3) + lrow;
                int ncol = wc + jp * 16 + ((grp & 2) << 2);
                ldsm_x4_trans(b[jp], bS + (krow * 72 + ncol) * 2);
            }
#pragma unroll
            for (int i = 0; i < 2; i++)
#pragma unroll
                for (int j = 0; j < 4; j++)
                    mma_f16(acc[i][j], a[i], &b[j >> 1][(j & 1) * 2]);
        }
        __syncthreads();
    }
    gemm_epilogue(acc, C, N, M, avs, avd, outs, outd, H, Cdim,
                  rowBase, colBase, wr, wc, g, tg);
}

// ---------------------------------------------------------------------------
// CSR build
// ---------------------------------------------------------------------------
__global__ void csr_count_kernel(const int* __restrict__ ei, int* __restrict__ deg,
                                 int* __restrict__ rank)
{
    int t = blockIdx.x * blockDim.x + threadIdx.x;
    if (t >= ETOT) return;
    int d = (t < EE) ? ei[EE + t] : (t - EE);
    rank[t] = atomicAdd(&deg[d], 1);
}

__global__ __launch_bounds__(1024) void csr_scan_kernel(
    int* __restrict__ deg, int* __restrict__ off)
{
    const int PER = 20;
    __shared__ int warpSums[32];
    int t    = threadIdx.x;
    int lane = t & 31, wid = t >> 5;
    int base = t * PER;

    int v[PER];
    int s = 0;
#pragma unroll
    for (int i = 0; i < PER; i++) {
        int idx = base + i;
        int x = (idx < NN) ? deg[idx] : 0;
        if (idx < NN) deg[idx] = 0;
        v[i] = s;
        s += x;
    }
    int incl = s;
#pragma unroll
    for (int o = 1; o < 32; o <<= 1) {
        int u = __shfl_up_sync(0xffffffffu, incl, o);
        if (lane >= o) incl += u;
    }
    if (lane == 31) warpSums[wid] = incl;
    __syncthreads();
    if (wid == 0) {
        int ws = warpSums[lane];
#pragma unroll
        for (int o = 1; o < 32; o <<= 1) {
            int u = __shfl_up_sync(0xffffffffu, ws, o);
            if (lane >= o) ws += u;
        }
        warpSums[lane] = ws;
    }
    __syncthreads();
    int warpPrefix  = (wid == 0) ? 0 : warpSums[wid - 1];
    int threadExcl  = warpPrefix + incl - s;
#pragma unroll
    for (int i = 0; i < PER; i++) {
        int idx = base + i;
        if (idx < NN) off[idx] = threadExcl + v[i];
    }
    if (t == 0) off[NN] = ETOT;
}

__global__ void csr_scatter_kernel(const int* __restrict__ ei,
                                   const int* __restrict__ off,
                                   const int* __restrict__ rank,
                                   int* __restrict__ csr_src)
{
    int t = blockIdx.x * blockDim.x + threadIdx.x;
    if (t >= ETOT) return;
    int s, d;
    if (t < EE) { s = ei[t]; d = ei[EE + t]; }
    else        { s = t - EE; d = s; }
    csr_src[off[d] + rank[t]] = s;
}

// ---------------------------------------------------------------------------
// GAT aggregation (H=4, C=64): ONE warp per dst; unroll-4; fp16 in AND out.
// ---------------------------------------------------------------------------
__global__ __launch_bounds__(256) void gat_gather4_kernel(
    const int* __restrict__ off, const int* __restrict__ csr_src,
    const __half* __restrict__ h,
    const float* __restrict__ as_, const float* __restrict__ ad_,
    const float* __restrict__ bias, __half* __restrict__ out)
{
    int gt   = blockIdx.x * blockDim.x + threadIdx.x;
    int d    = gt >> 5;
    int lane = gt & 31;
    if (d >= NN) return;

    const int head = lane >> 3;
    const uint4* hb = reinterpret_cast<const uint4*>(h);
    float adv = ad_[d * 4 + head];

    float acc[8];
#pragma unroll
    for (int k = 0; k < 8; k++) acc[k] = 0.f;
    float den = 0.f;

    int a   = off[d];
    int end = off[d + 1];
    for (; a + 3 < end; a += 4) {
        int s0 = csr_src[a];
        int s1 = csr_src[a + 1];
        int s2 = csr_src[a + 2];
        int s3 = csr_src[a + 3];
        float e0 = as_[s0 * 4 + head] + adv;
        float e1 = as_[s1 * 4 + head] + adv;
        float e2 = as_[s2 * 4 + head] + adv;
        float e3 = as_[s3 * 4 + head] + adv;
        uint4 v0 = hb[(size_t)s0 * 32 + lane];
        uint4 v1 = hb[(size_t)s1 * 32 + lane];
        uint4 v2 = hb[(size_t)s2 * 32 + lane];
        uint4 v3 = hb[(size_t)s3 * 32 + lane];
        e0 = e0 > 0.f ? e0 : 0.2f * e0;
        e1 = e1 > 0.f ? e1 : 0.2f * e1;
        e2 = e2 > 0.f ? e2 : 0.2f * e2;
        e3 = e3 > 0.f ? e3 : 0.2f * e3;
        float x0 = __expf(e0);
        float x1 = __expf(e1);
        float x2 = __expf(e2);
        float x3 = __expf(e3);
        h8_accum(acc, v0, x0);
        h8_accum(acc, v1, x1);
        h8_accum(acc, v2, x2);
        h8_accum(acc, v3, x3);
        den += (x0 + x1) + (x2 + x3);
    }
    for (; a < end; a++) {
        int s = csr_src[a];
        float e = as_[s * 4 + head] + adv;
        uint4 v = hb[(size_t)s * 32 + lane];
        e = e > 0.f ? e : 0.2f * e;
        float ex = __expf(e);
        h8_accum(acc, v, ex);
        den += ex;
    }

    float r = 1.f / (den + 1e-16f);
    float4 b0 = *reinterpret_cast<const float4*>(&bias[lane * 8]);
    float4 b1 = *reinterpret_cast<const float4*>(&bias[lane * 8 + 4]);
    float o[8];
    o[0] = acc[0] * r + b0.x; o[1] = acc[1] * r + b0.y;
    o[2] = acc[2] * r + b0.z; o[3] = acc[3] * r + b0.w;
    o[4] = acc[4] * r + b1.x; o[5] = acc[5] * r + b1.y;
    o[6] = acc[6] * r + b1.z; o[7] = acc[7] * r + b1.w;
#pragma unroll
    for (int k = 0; k < 8; k++) o[k] = o[k] > 0.f ? o[k] : expm1f(o[k]);

    uint4 ov;
    ov.x = h2_as_u32(__floats2half2_rn(o[0], o[1]));
    ov.y = h2_as_u32(__floats2half2_rn(o[2], o[3]));
    ov.z = h2_as_u32(__floats2half2_rn(o[4], o[5]));
    ov.w = h2_as_u32(__floats2half2_rn(o[6], o[7]));
    reinterpret_cast<uint4*>(out + (size_t)d * HC12)[lane] = ov;
}

// ---------------------------------------------------------------------------
// GAT aggregation (H=1, C=128): ONE warp per dst; unroll-4; fp32 out.
// ---------------------------------------------------------------------------
__global__ __launch_bounds__(256) void gat_gather1_kernel(
    const int* __restrict__ off, const int* __restrict__ csr_src,
    const __half* __restrict__ h,
    const float* __restrict__ as_, const float* __restrict__ ad_,
    const float* __restrict__ bias, float* __restrict__ out)
{
    int gt   = blockIdx.x * blockDim.x + threadIdx.x;
    int d    = gt >> 5;
    int lane = gt & 31;
    if (d >= NN) return;

    const uint2* hb = reinterpret_cast<const uint2*>(h);
    float adv = ad_[d];
    float acc[4] = {0.f, 0.f, 0.f, 0.f};
    float den = 0.f;

    int a   = off[d];
    int end = off[d + 1];
    for (; a + 3 < end; a += 4) {
        int s0 = csr_src[a];
        int s1 = csr_src[a + 1];
        int s2 = csr_src[a + 2];
        int s3 = csr_src[a + 3];
        float e0 = as_[s0] + adv;
        float e1 = as_[s1] + adv;
        float e2 = as_[s2] + adv;
        float e3 = as_[s3] + adv;
        uint2 v0 = hb[(size_t)s0 * 32 + lane];
        uint2 v1 = hb[(size_t)s1 * 32 + lane];
        uint2 v2 = hb[(size_t)s2 * 32 + lane];
        uint2 v3 = hb[(size_t)s3 * 32 + lane];
        e0 = e0 > 0.f ? e0 : 0.2f * e0;
        e1 = e1 > 0.f ? e1 : 0.2f * e1;
        e2 = e2 > 0.f ? e2 : 0.2f * e2;
        e3 = e3 > 0.f ? e3 : 0.2f * e3;
        float x0 = __expf(e0);
        float x1 = __expf(e1);
        float x2 = __expf(e2);
        float x3 = __expf(e3);
        h4_accum(acc, v0, x0);
        h4_accum(acc, v1, x1);
        h4_accum(acc, v2, x2);
        h4_accum(acc, v3, x3);
        den += (x0 + x1) + (x2 + x3);
    }
    for (; a < end; a++) {
        int s = csr_src[a];
        float e = as_[s] + adv;
        uint2 v = hb[(size_t)s * 32 + lane];
        e = e > 0.f ? e : 0.2f * e;
        float ex = __expf(e);
        h4_accum(acc, v, ex);
        den += ex;
    }

    float r = 1.f / (den + 1e-16f);
    float4 b = *reinterpret_cast<const float4*>(&bias[lane * 4]);
    float4 o;
    o.x = acc[0] * r + b.x; o.y = acc[1] * r + b.y;
    o.z = acc[2] * r + b.z; o.w = acc[3] * r + b.w;
    reinterpret_cast<float4*>(out + (size_t)d * FOUT)[lane] = o;
}

// ---------------------------------------------------------------------------
// Segmented global mean pool (batch sorted)
// ---------------------------------------------------------------------------
__global__ __launch_bounds__(128) void pool_kernel(
    const float* __restrict__ h, const int* __restrict__ bat,
    float* __restrict__ out_emb)
{
    int g = blockIdx.x;
    int c = threadIdx.x;

    int lo = 0, hi = NN;
    while (lo < hi) { int m = (lo + hi) >> 1; if (bat[m] < g) lo = m + 1; else hi = m; }
    int start = lo;
    lo = 0; hi = NN;
    while (lo < hi) { int m = (lo + hi) >> 1; if (bat[m] < g + 1) lo = m + 1; else hi = m; }
    int end = lo;

    float s0 = 0.f, s1 = 0.f, s2 = 0.f, s3 = 0.f;
    int n = start;
    for (; n + 3 < end; n += 4) {
        s0 += h[(size_t)n * FOUT + c];
        s1 += h[(size_t)(n + 1) * FOUT + c];
        s2 += h[(size_t)(n + 2) * FOUT + c];
        s3 += h[(size_t)(n + 3) * FOUT + c];
    }
    for (; n < end; n++) s0 += h[(size_t)n * FOUT + c];
    float s = (s0 + s1) + (s2 + s3);
    out_emb[g * FOUT + c] = s / fmaxf((float)(end - start), 1.f);
}

// ---------------------------------------------------------------------------
// zero alpha buffers
// ---------------------------------------------------------------------------
__global__ void zero_alpha_kernel(float* __restrict__ a, float* __restrict__ b)
{
    int t = blockIdx.x * blockDim.x + threadIdx.x;
    if (t < NN * HEADS) { a[t] = 0.f; b[t] = 0.f; }
}

// ---------------------------------------------------------------------------
// Launch
// ---------------------------------------------------------------------------
extern "C" void kernel_launch(void* const* d_in, const int* in_sizes, int n_in,
                              void* d_out, int out_size)
{
    const float* x   = (const float*)d_in[0];
    const int*   ei  = (const int*)d_in[1];
    const int*   bat = (const int*)d_in[2];
    const float* W1  = (const float*)d_in[3];
    const float* as1 = (const float*)d_in[4];
    const float* ad1 = (const float*)d_in[5];
    const float* b1  = (const float*)d_in[6];
    const float* W2  = (const float*)d_in[7];
    const float* as2 = (const float*)d_in[8];
    const float* ad2 = (const float*)d_in[9];
    const float* b2  = (const float*)d_in[10];
    const float* W3  = (const float*)d_in[11];
    const float* as3 = (const float*)d_in[12];
    const float* ad3 = (const float*)d_in[13];
    const float* b3  = (const float*)d_in[14];

    float* out     = (float*)d_out;
    float* out_emb = out;                 // [G, FOUT]
    float* out_h   = out + GG * FOUT;     // [N, FOUT]

    __half *h16, *b16, *w16;
    float *asA, *adA, *asB, *adB;
    int *deg, *off, *rank, *csr_src;
    cudaGetSymbolAddress((void**)&h16,  g_h16);
    cudaGetSymbolAddress((void**)&b16,  g_b16);
    cudaGetSymbolAddress((void**)&w16,  g_w16);
    cudaGetSymbolAddress((void**)&asA,  g_asA);
    cudaGetSymbolAddress((void**)&adA,  g_adA);
    cudaGetSymbolAddress((void**)&asB,  g_asB);
    cudaGetSymbolAddress((void**)&adB,  g_adB);
    cudaGetSymbolAddress((void**)&deg,  g_deg);
    cudaGetSymbolAddress((void**)&off,  g_off);
    cudaGetSymbolAddress((void**)&rank, g_rank);
    cudaGetSymbolAddress((void**)&csr_src, g_csr_src);

    __half* w16_1 = w16;
    __half* w16_2 = w16 + 32768;
    __half* w16_3 = w16 + 98304;

    static cudaStream_t sideStream = nullptr;
    static cudaEvent_t evFork = nullptr, evW1 = nullptr, evJoin = nullptr, evJoin2 = nullptr;
    if (sideStream == nullptr) {
        cudaStreamCreateWithFlags(&sideStream, cudaStreamNonBlocking);
        cudaEventCreateWithFlags(&evFork, cudaEventDisableTiming);
        cudaEventCreateWithFlags(&evW1, cudaEventDisableTiming);
        cudaEventCreateWithFlags(&evJoin, cudaEventDisableTiming);
        cudaEventCreateWithFlags(&evJoin2, cudaEventDisableTiming);
    }

    // --- fork: side stream does W1 cvt + asA/adA zero, then CSR + W2/W3 ---
    cudaEventRecord(evFork, 0);
    cudaStreamWaitEvent(sideStream, evFork, 0);
    cvt_w1_kernel<<<(NN * HEADS + 255) / 256, 256, 0, sideStream>>>(
        (const float4*)W1, (uint2*)w16, asA, adA);
    cudaEventRecord(evW1, sideStream);
    csr_count_kernel<<<(ETOT + 255) / 256, 256, 0, sideStream>>>(ei, deg, rank);
    csr_scan_kernel<<<1, 1024, 0, sideStream>>>(deg, off);
    csr_scatter_kernel<<<(ETOT + 255) / 256, 256, 0, sideStream>>>(ei, off, rank, csr_src);
    cvt_side_kernel<<<(NN * HEADS + 255) / 256, 256, 0, sideStream>>>(
        (const float4*)W2, (const float4*)W3, (uint2*)w16, asB, adB);
    cudaEventRecord(evJoin, sideStream);

    const int nby = (NN + 127) / 128;
    const int gatherGrid = (NN * 32 + 255) / 256;

    // --- main stream: layer-1 GEMM directly on fp32 x ---
    cudaStreamWaitEvent(0, evW1, 0);
    gemm1_tc_kernel<<<dim3(HC12 / 64, nby), 256>>>(x, w16_1, h16, as1, ad1, asA, adA);

    cudaStreamWaitEvent(0, evJoin, 0);
    gat_gather4_kernel<<<gatherGrid, 256>>>(off, csr_src, h16, asA, adA, b1, b16);

    // side: re-zero asA/adA for layer 3 while layer 2 runs on main
    cudaEventRecord(evFork, 0);
    cudaStreamWaitEvent(sideStream, evFork, 0);
    zero_alpha_kernel<<<(NN * HEADS + 255) / 256, 256, 0, sideStream>>>(asA, adA);
    cudaEventRecord(evJoin2, sideStream);

    // --- Layer 2 ---
    gemm_tc_kernel<<<dim3(HC12 / 64, nby), 256>>>(b16, w16_2, h16, NN, HC12, HC12,
                                                  as2, ad2, asB, adB, HEADS, HID);
    gat_gather4_kernel<<<gatherGrid, 256>>>(off, csr_src, h16, asB, adB, b2, b16);

    cudaStreamWaitEvent(0, evJoin2, 0);

    // --- Layer 3 ---
    gemm_tc_kernel<<<dim3(FOUT / 64, nby), 256>>>(b16, w16_3, h16, NN, HC12, FOUT,
                                                  as3, ad3, asA, adA, 1, FOUT);
    gat_gather1_kernel<<<gatherGrid, 256>>>(off, csr_src, h16, asA, adA, b3, out_h);

    // --- segmented global mean pool ---
    pool_kernel<<<GG, 128>>>(out_h, bat, out_emb);
}